// round 8
// baseline (speedup 1.0000x reference)
#include <cuda_runtime.h>
#include <cuda_fp16.h>
#include <cstdint>

// ============================================================================
// out[b,l,d] = sum_{i,j} x0[b,i,d]*x1[b,j,d]*filters[i*64+j, l]
// B=2048, F1=F2=64, D=16, L=16.
//
// R8: instruction-roofline fix. Four rounds showed legacy HMMA.f32-acc is
// capped at ~26 cyc/SMSP on sm_100 regardless of feeding. Switch the inner
// product to f16-ACCUMULATE mma (historically 2x rate), in 2-kstep groups
// (32 j's) promoted to fp32 master accumulators with the x0 fold (fp32 FFMA,
// removing x0-fp16 error and all HMUL2s). R7 skeleton otherwise.
// ============================================================================

// Pre-arranged W fragment image: [i(64)][kstep(4)][lane(32)] x 16B.
__device__ __align__(16) uint4 g_Wfrag[64 * 4 * 32];

__device__ __forceinline__ uint32_t pack_half2(float a, float b) {
    __half2 h = __floats2half2_rn(a, b);   // .x (low 16b) = a, .y = b
    return *(uint32_t*)&h;
}

// f16-accumulate MMA: D(f16) = A(f16)@B(f16) + C(f16). C/D = 2 regs (4 halves):
// reg0 = {row gid,   cols 2q,2q+1}, reg1 = {row gid+8, cols 2q,2q+1}.
__device__ __forceinline__ void mma16816_f16(uint32_t c[2], const uint4& a, const uint2& b) {
    asm volatile(
        "mma.sync.aligned.m16n8k16.row.col.f16.f16.f16.f16 "
        "{%0,%1}, {%2,%3,%4,%5}, {%6,%7}, {%0,%1};\n"
        : "+r"(c[0]), "+r"(c[1])
        : "r"(a.x), "r"(a.y), "r"(a.z), "r"(a.w), "r"(b.x), "r"(b.y));
}

// ---------------------------------------------------------- prep kernel -----
// A-fragment mapping (m16k16, row-major), lane = 4*gid + q:
//   reg0 = {A[gid][2q],   A[gid][2q+1]}    reg1 = {A[gid+8][2q],   A[gid+8][2q+1]}
//   reg2 = {A[gid][2q+8], A[gid][2q+9]}    reg3 = {A[gid+8][2q+8], A[gid+8][2q+9]}
// A row = l; A col = k = j (global j = 16*kstep + local).
__global__ void prep_w_kernel(const float* __restrict__ filters) {
    int idx  = blockIdx.x * 256 + threadIdx.x;    // 8192 total
    int i    = (idx >> 7) & 63;
    int t    = (idx >> 5) & 3;
    int lane = idx & 31;
    int gid = lane >> 2, q = lane & 3;
    int k0 = t * 16 + q * 2;
    int l0 = gid, l1 = gid + 8;

    float e[8];
    int ls[8] = {l0, l0, l1, l1, l0, l0, l1, l1};
    int ks[8] = {k0, k0 + 1, k0, k0 + 1, k0 + 8, k0 + 9, k0 + 8, k0 + 9};
    #pragma unroll
    for (int j = 0; j < 8; ++j)
        e[j] = filters[(i * 64 + ks[j]) * 16 + ls[j]];

    g_Wfrag[idx] = make_uint4(pack_half2(e[0], e[1]), pack_half2(e[2], e[3]),
                              pack_half2(e[4], e[5]), pack_half2(e[6], e[7]));
}

// ------------------------------------------------------------ main kernel ---
// SMEM: x0e (32KB, persists) | raw staging 32KB (becomes wb after mainloop)
static constexpr int SM_X0E = 0;        // 4096 float2: x0 pairs [i*64+mc*4+q]
static constexpr int SM_RAW = 32768;    // staging; wb overlay after mainloop
static constexpr int SMEM_TOTAL = 65536;

__global__ __launch_bounds__(256, 2) void fm_main_kernel(
    const float* __restrict__ x0g,
    const float* __restrict__ x1g,
    float* __restrict__ outg)
{
    extern __shared__ __align__(16) unsigned char smem[];
    float2*  x0e  = (float2*)(smem + SM_X0E);
    float*   raw  = (float*)(smem + SM_RAW);
    float4*  raw4 = (float4*)(smem + SM_RAW);
    float*   wb   = (float*)(smem + SM_RAW);   // after mainloop

    int tid = threadIdx.x;
    int w = tid >> 5, lane = tid & 31;
    int gid = lane >> 2, q = lane & 3;
    int Q = w & 3;         // mc-quarter: mc = Q*4 + mcl
    int h = w >> 2;        // i-half: i = h*32 + il
    int bbase = blockIdx.x * 8;   // 8 b's -> 128 (b,d) rows per CTA

    // ---- stage x1 slab coalesced, then build register-resident B frags ----
    const float4* x1s = (const float4*)(x1g + (size_t)bbase * 1024);
    for (int e = tid; e < 2048; e += 256) raw4[e] = x1s[e];
    __syncthreads();

    // B fragment (mcl, t): lane holds {x1[r][k0], [k0+1], [k0+8], [k0+9]},
    // r = (Q*4+mcl)*8 + gid (the n8 dim = m rows), k0 = 16t + 2q.
    uint2 Bf[4][4];
    #pragma unroll
    for (int mcl = 0; mcl < 4; ++mcl) {
        int r = (Q * 4 + mcl) * 8 + gid;
        int bl = r >> 4, d = r & 15;
        const float* base = raw + bl * 1024 + d;
        #pragma unroll
        for (int t = 0; t < 4; ++t) {
            int k0 = t * 16 + q * 2;
            float f0 = base[k0 * 16];
            float f1 = base[(k0 + 1) * 16];
            float f2 = base[(k0 + 8) * 16];
            float f3 = base[(k0 + 9) * 16];
            Bf[mcl][t] = make_uint2(pack_half2(f0, f1), pack_half2(f2, f3));
        }
    }
    __syncthreads();

    // ---- stage x0 slab, build fp32 epilogue pairs x0e[i*64 + mc*4 + q] ----
    const float4* x0s = (const float4*)(x0g + (size_t)bbase * 1024);
    for (int e = tid; e < 2048; e += 256) raw4[e] = x0s[e];
    __syncthreads();
    for (int e = tid; e < 4096; e += 256) {
        int i = e >> 6, mc = (e >> 2) & 15, q2 = e & 3;
        int m0 = mc * 8 + q2 * 2;
        int bl = m0 >> 4, d = m0 & 15;     // m0 even -> m0+1 same b
        const float* base = raw + bl * 1024 + i * 16 + d;
        x0e[e] = make_float2(base[0], base[1]);
    }
    __syncthreads();

    // ---- mainloop: 32 i's; f16-acc groups of 2 ksteps -> fp32 fold ----
    float acc[4][4];
    #pragma unroll
    for (int mcl = 0; mcl < 4; ++mcl)
        #pragma unroll
        for (int r = 0; r < 4; ++r) acc[mcl][r] = 0.0f;

    const uint4* wp = g_Wfrag + lane;
    int i0 = h * 32;
    uint4 Wc[4], Wn[4];
    #pragma unroll
    for (int t = 0; t < 4; ++t) Wc[t] = wp[(i0 * 4 + t) * 32];

    for (int il = 0; il < 32; ++il) {
        int i = i0 + il;
        if (il < 31) {
            #pragma unroll
            for (int t = 0; t < 4; ++t) Wn[t] = wp[((i + 1) * 4 + t) * 32];
        }
        const float2* xp = x0e + i * 64 + Q * 16 + q;
        #pragma unroll
        for (int mcl = 0; mcl < 4; ++mcl) {
            float2 xv = xp[mcl * 4];
            #pragma unroll
            for (int grp = 0; grp < 2; ++grp) {
                uint32_t c16[2] = {0u, 0u};
                mma16816_f16(c16, Wc[grp * 2],     Bf[mcl][grp * 2]);
                mma16816_f16(c16, Wc[grp * 2 + 1], Bf[mcl][grp * 2 + 1]);
                float2 f0 = __half22float2(*(__half2*)&c16[0]);   // l=gid
                float2 f1 = __half22float2(*(__half2*)&c16[1]);   // l=gid+8
                acc[mcl][0] = fmaf(xv.x, f0.x, acc[mcl][0]);
                acc[mcl][1] = fmaf(xv.y, f0.y, acc[mcl][1]);
                acc[mcl][2] = fmaf(xv.x, f1.x, acc[mcl][2]);
                acc[mcl][3] = fmaf(xv.y, f1.y, acc[mcl][3]);
            }
        }
        #pragma unroll
        for (int t = 0; t < 4; ++t) Wc[t] = Wn[t];
    }

    // ---- partial writeback: wb[(w*4+mcl)*136 + l*8 + mloc] (pad kills conflicts)
    #pragma unroll
    for (int mcl = 0; mcl < 4; ++mcl) {
        float* bptr = wb + (w * 4 + mcl) * 136;
        *(float2*)&bptr[gid * 8 + 2 * q]       = make_float2(acc[mcl][0], acc[mcl][1]);
        *(float2*)&bptr[(gid + 8) * 8 + 2 * q] = make_float2(acc[mcl][2], acc[mcl][3]);
    }
    __syncthreads();

    // ---- 2-way reduce (i-halves) + coalesced store ----
    for (int o = tid; o < 2048; o += 256) {
        int l = o >> 7, m = o & 127;
        int Q2 = m >> 5, mcl = (m >> 3) & 3, mloc = m & 7;
        int off = (Q2 * 4 + mcl) * 136 + l * 8 + mloc;
        float s = wb[off] + wb[off + 16 * 136];   // partner warp w+4
        int bl = m >> 4, d = m & 15;
        outg[(size_t)(bbase + bl) * 256 + l * 16 + d] = s;
    }
}

// ------------------------------------------------------------------ launch --
extern "C" void kernel_launch(void* const* d_in, const int* in_sizes, int n_in,
                              void* d_out, int out_size) {
    const float* x0 = (const float*)d_in[0];
    const float* x1 = (const float*)d_in[1];
    const float* filters = (const float*)d_in[2];
    float* out = (float*)d_out;

    cudaFuncSetAttribute(fm_main_kernel,
                         cudaFuncAttributeMaxDynamicSharedMemorySize, SMEM_TOTAL);

    prep_w_kernel<<<32, 256>>>(filters);
    fm_main_kernel<<<256, 256, SMEM_TOTAL>>>(x0, x1, out);
}